// round 2
// baseline (speedup 1.0000x reference)
#include <cuda_runtime.h>
#include <math.h>

// Problem constants
#define B_  2
#define S_  2048
#define D_  2048
#define H_  16
#define HD_ 128
#define M_  (B_*S_)   // 4096 rows

// Flash-attention tiling
#define BR 64
#define BC 64
#define QK_PAD 68     // padded row length for transposed Q/K tiles [HD][BR+pad]
#define V_PAD  132    // padded row length for V tile [BC][HD+pad]
#define S_PAD  68     // padded row length for score tile [BR][BC+pad]

// Scratch (device globals: allocation-free rule)
__device__ float g_q[(size_t)M_ * D_];    // Q in (B,H,S,HD) layout
__device__ float g_ctx[(size_t)M_ * D_];  // attention context in (B,S,D) layout

// ---------------------------------------------------------------------------
// GEMM: Y = X @ W^T + bias.  X:[M,K] row-major, W:[N,K] row-major.
// reshape==0: Y row-major [M,N]  (M=B*S, N=D)
// reshape==1: Y written as (B,H,S,HD) from m=b*S+s, n=h*HD+hd
// Tiling: 128x128 block, K-step 16, 256 threads, 8x8 per-thread micro-tile.
// ---------------------------------------------------------------------------
__global__ __launch_bounds__(256) void gemm_nt(const float* __restrict__ X,
                                               const float* __restrict__ W,
                                               const float* __restrict__ bias,
                                               float* __restrict__ Y,
                                               int reshape)
{
    __shared__ float As[16][128];
    __shared__ float Bs[16][128];
    const int K  = D_;
    const int m0 = blockIdx.y * 128;
    const int n0 = blockIdx.x * 128;
    const int tid = threadIdx.x;
    const int tx = tid & 15;
    const int ty = tid >> 4;

    float acc[8][8];
#pragma unroll
    for (int i = 0; i < 8; i++)
#pragma unroll
        for (int j = 0; j < 8; j++) acc[i][j] = 0.f;

    for (int k0 = 0; k0 < K; k0 += 16) {
        // Load 128x16 tiles of X and W (transposed into smem [k][row]).
#pragma unroll
        for (int l = 0; l < 2; ++l) {
            int f  = tid + l * 256;
            int i  = f >> 2;
            int k4 = (f & 3) << 2;
            float4 va = *reinterpret_cast<const float4*>(X + (size_t)(m0 + i) * K + k0 + k4);
            As[k4 + 0][i] = va.x; As[k4 + 1][i] = va.y;
            As[k4 + 2][i] = va.z; As[k4 + 3][i] = va.w;
            float4 vb = *reinterpret_cast<const float4*>(W + (size_t)(n0 + i) * K + k0 + k4);
            Bs[k4 + 0][i] = vb.x; Bs[k4 + 1][i] = vb.y;
            Bs[k4 + 2][i] = vb.z; Bs[k4 + 3][i] = vb.w;
        }
        __syncthreads();

#pragma unroll
        for (int kk = 0; kk < 16; ++kk) {
            float a[8], b[8];
            *reinterpret_cast<float4*>(&a[0]) = *reinterpret_cast<const float4*>(&As[kk][ty * 8]);
            *reinterpret_cast<float4*>(&a[4]) = *reinterpret_cast<const float4*>(&As[kk][ty * 8 + 4]);
            *reinterpret_cast<float4*>(&b[0]) = *reinterpret_cast<const float4*>(&Bs[kk][tx * 8]);
            *reinterpret_cast<float4*>(&b[4]) = *reinterpret_cast<const float4*>(&Bs[kk][tx * 8 + 4]);
#pragma unroll
            for (int i = 0; i < 8; i++)
#pragma unroll
                for (int j = 0; j < 8; j++)
                    acc[i][j] = fmaf(a[i], b[j], acc[i][j]);
        }
        __syncthreads();
    }

#pragma unroll
    for (int i = 0; i < 8; i++) {
        int m = m0 + ty * 8 + i;
#pragma unroll
        for (int j = 0; j < 8; j++) {
            int n = n0 + tx * 8 + j;
            float v = acc[i][j] + bias[n];
            size_t idx;
            if (reshape) {
                int bb = m >> 11;            // /S_
                int ss = m & (S_ - 1);
                int hh = n >> 7;             // /HD_
                int hd = n & (HD_ - 1);
                idx = (((size_t)(bb * H_ + hh)) * S_ + ss) * HD_ + hd;
            } else {
                idx = (size_t)m * D_ + n;
            }
            Y[idx] = v;
        }
    }
}

// ---------------------------------------------------------------------------
// Causal flash attention, fp32.
// Q,K,V in (B,H,S,HD).  ctx out in (B,S,D).
// Block: 256 threads handles BR=64 query rows; loops causally over BC=64
// key tiles.  O accumulator: per-thread 4 rows x 8 cols in registers.
// ---------------------------------------------------------------------------
__global__ __launch_bounds__(256) void flash_attn(const float* __restrict__ Qg,
                                                  const float* __restrict__ Kg,
                                                  const float* __restrict__ Vg,
                                                  float* __restrict__ ctx)
{
    extern __shared__ float smf[];
    float* Qt   = smf;                        // [128][QK_PAD] transposed Q tile
    float* Kt   = Qt + 128 * QK_PAD;          // [128][QK_PAD] transposed K tile
    float* Vs   = Kt + 128 * QK_PAD;          // [64][V_PAD]   V tile row-major
    float* Ss   = Vs + 64 * V_PAD;            // [64][S_PAD]   scores / probs
    float* mrow = Ss + 64 * S_PAD;            // [64] running max
    float* lrow = mrow + 64;                  // [64] running sum
    float* arow = lrow + 64;                  // [64] rescale factor

    const int bh   = blockIdx.y;              // b*H + h
    const int qt_i = blockIdx.x;
    const int q0   = qt_i * BR;
    const int tid  = threadIdx.x;
    const int tx   = tid & 15;
    const int ty   = tid >> 4;

    const float* Qb = Qg + ((size_t)bh * S_ + q0) * HD_;
    const float* Kb = Kg + (size_t)bh * S_ * HD_;
    const float* Vb = Vg + (size_t)bh * S_ * HD_;

    // Load Q tile, transposed into Qt[k][row].
#pragma unroll
    for (int l = 0; l < 8; ++l) {
        int f   = tid + l * 256;
        int row = f >> 5;
        int c4  = (f & 31) << 2;
        float4 v = *reinterpret_cast<const float4*>(Qb + (size_t)row * HD_ + c4);
        Qt[(c4 + 0) * QK_PAD + row] = v.x;
        Qt[(c4 + 1) * QK_PAD + row] = v.y;
        Qt[(c4 + 2) * QK_PAD + row] = v.z;
        Qt[(c4 + 3) * QK_PAD + row] = v.w;
    }
    if (tid < 64) { mrow[tid] = -1e30f; lrow[tid] = 0.f; }

    float o[4][8];
#pragma unroll
    for (int i = 0; i < 4; i++)
#pragma unroll
        for (int c = 0; c < 8; c++) o[i][c] = 0.f;

    const float scale = 0.08838834764831845f;  // 1/sqrt(128)

    const int ntiles = qt_i + 1;               // causal: only k-tiles <= q-tile
    for (int t = 0; t < ntiles; ++t) {
        const int k0 = t * BC;
        __syncthreads();   // previous iter's Ss/Vs readers done before overwrite

        // Load K tile transposed + V tile row-major.
#pragma unroll
        for (int l = 0; l < 8; ++l) {
            int f   = tid + l * 256;
            int row = f >> 5;
            int c4  = (f & 31) << 2;
            float4 kv = *reinterpret_cast<const float4*>(Kb + (size_t)(k0 + row) * HD_ + c4);
            Kt[(c4 + 0) * QK_PAD + row] = kv.x;
            Kt[(c4 + 1) * QK_PAD + row] = kv.y;
            Kt[(c4 + 2) * QK_PAD + row] = kv.z;
            Kt[(c4 + 3) * QK_PAD + row] = kv.w;
            float4 vv = *reinterpret_cast<const float4*>(Vb + (size_t)(k0 + row) * HD_ + c4);
            *reinterpret_cast<float4*>(Vs + row * V_PAD + c4) = vv;
        }
        __syncthreads();

        // S = Q @ K^T  (per-thread 4x4)
        float sacc[4][4];
#pragma unroll
        for (int i = 0; i < 4; i++)
#pragma unroll
            for (int j = 0; j < 4; j++) sacc[i][j] = 0.f;

#pragma unroll 4
        for (int kk = 0; kk < HD_; ++kk) {
            float4 a4 = *reinterpret_cast<const float4*>(Qt + kk * QK_PAD + ty * 4);
            float4 b4 = *reinterpret_cast<const float4*>(Kt + kk * QK_PAD + tx * 4);
            float a[4] = {a4.x, a4.y, a4.z, a4.w};
            float b[4] = {b4.x, b4.y, b4.z, b4.w};
#pragma unroll
            for (int i = 0; i < 4; i++)
#pragma unroll
                for (int j = 0; j < 4; j++)
                    sacc[i][j] = fmaf(a[i], b[j], sacc[i][j]);
        }

        // Scale + causal mask (only diagonal tile needs masking), stash scores.
        const bool diag = (k0 == q0);
#pragma unroll
        for (int i = 0; i < 4; i++) {
#pragma unroll
            for (int j = 0; j < 4; j++) {
                float v = sacc[i][j] * scale;
                if (diag && (tx * 4 + j) > (ty * 4 + i)) v += -1e9f;
                Ss[(ty * 4 + i) * S_PAD + tx * 4 + j] = v;
            }
        }
        __syncthreads();

        // Online softmax per row (one thread per row).
        if (tid < 64) {
            float* srow = Ss + tid * S_PAD;
            float tm = srow[0];
#pragma unroll 8
            for (int j = 1; j < BC; ++j) tm = fmaxf(tm, srow[j]);
            float mo = mrow[tid];
            float mn = fmaxf(mo, tm);
            float al = __expf(mo - mn);
            float sum = 0.f;
#pragma unroll 8
            for (int j = 0; j < BC; ++j) {
                float p = __expf(srow[j] - mn);
                srow[j] = p;
                sum += p;
            }
            lrow[tid] = lrow[tid] * al + sum;
            mrow[tid] = mn;
            arow[tid] = al;
        }
        __syncthreads();

        // Rescale O, accumulate P @ V  (per-thread 4 rows x 8 cols).
        float al[4];
#pragma unroll
        for (int i = 0; i < 4; i++) al[i] = arow[ty * 4 + i];
#pragma unroll
        for (int i = 0; i < 4; i++)
#pragma unroll
            for (int c = 0; c < 8; c++) o[i][c] *= al[i];

#pragma unroll 4
        for (int j = 0; j < BC; ++j) {
            float p[4];
#pragma unroll
            for (int i = 0; i < 4; i++) p[i] = Ss[(ty * 4 + i) * S_PAD + j];
            float4 v0 = *reinterpret_cast<const float4*>(Vs + j * V_PAD + tx * 8);
            float4 v1 = *reinterpret_cast<const float4*>(Vs + j * V_PAD + tx * 8 + 4);
            float vv[8] = {v0.x, v0.y, v0.z, v0.w, v1.x, v1.y, v1.z, v1.w};
#pragma unroll
            for (int i = 0; i < 4; i++)
#pragma unroll
                for (int c = 0; c < 8; c++)
                    o[i][c] = fmaf(p[i], vv[c], o[i][c]);
        }
    }

    // Normalize and write ctx in (B,S,D) layout.
    const int bb = bh / H_;
    const int hh = bh % H_;
#pragma unroll
    for (int i = 0; i < 4; i++) {
        int r = ty * 4 + i;
        float inv = 1.0f / lrow[r];
        float* dst = ctx + ((size_t)bb * S_ + q0 + r) * D_ + hh * HD_ + tx * 8;
        float4 w0 = make_float4(o[i][0] * inv, o[i][1] * inv, o[i][2] * inv, o[i][3] * inv);
        float4 w1 = make_float4(o[i][4] * inv, o[i][5] * inv, o[i][6] * inv, o[i][7] * inv);
        *reinterpret_cast<float4*>(dst)     = w0;
        *reinterpret_cast<float4*>(dst + 4) = w1;
    }
}

// ---------------------------------------------------------------------------
// kernel_launch: QKV proj -> flash attention -> O proj.
// Outputs packed: out (B,S,D) @0, k (B,H,S,HD) @OFF, v @2*OFF.
// ---------------------------------------------------------------------------
extern "C" void kernel_launch(void* const* d_in, const int* in_sizes, int n_in,
                              void* d_out, int out_size)
{
    const float* X  = (const float*)d_in[0];
    // d_in[1] = attn_mask (pure causal; applied analytically)
    const float* Wq = (const float*)d_in[2];
    const float* bq = (const float*)d_in[3];
    const float* Wk = (const float*)d_in[4];
    const float* bk = (const float*)d_in[5];
    const float* Wv = (const float*)d_in[6];
    const float* bv = (const float*)d_in[7];
    const float* Wo = (const float*)d_in[8];
    const float* bo = (const float*)d_in[9];

    float* out = (float*)d_out;
    const size_t OFF = (size_t)B_ * S_ * D_;
    float* kout = out + OFF;
    float* vout = out + 2 * OFF;

    // One-time host setup (idempotent; not per-call work).
    static float* qbuf = nullptr;
    static float* cbuf = nullptr;
    static const int SMEM = (2 * 128 * QK_PAD + 64 * V_PAD + 64 * S_PAD + 3 * 64) * (int)sizeof(float);
    if (qbuf == nullptr) {
        cudaGetSymbolAddress((void**)&qbuf, g_q);
        cudaGetSymbolAddress((void**)&cbuf, g_ctx);
        cudaFuncSetAttribute(flash_attn, cudaFuncAttributeMaxDynamicSharedMemorySize, SMEM);
    }

    dim3 gg(D_ / 128, M_ / 128);   // (16, 32)
    gemm_nt<<<gg, 256>>>(X, Wq, bq, qbuf, 1);
    gemm_nt<<<gg, 256>>>(X, Wk, bk, kout, 1);
    gemm_nt<<<gg, 256>>>(X, Wv, bv, vout, 1);

    flash_attn<<<dim3(S_ / BR, B_ * H_), 256, SMEM>>>(qbuf, kout, vout, cbuf);

    gemm_nt<<<gg, 256>>>(cbuf, Wo, bo, out, 0);
}

// round 3
// speedup vs baseline: 1.9413x; 1.9413x over previous
#include <cuda_runtime.h>
#include <math.h>
#include <stdint.h>

// Problem constants
#define B_  2
#define S_  2048
#define D_  2048
#define H_  16
#define HD_ 128
#define M_  (B_*S_)   // 4096 rows

// GEMM tiling (tf32 tensor-core path)
#define BM 128
#define BN 128
#define BK 32
#define LDW 36        // BK + 4 pad words: conflict-free fragment loads

// Flash-attention tiling
#define BR 64
#define BC 64
#define QK_PAD 68
#define V_PAD  132
#define S_PAD  68

// Scratch (device globals: allocation-free rule)
__device__ float g_q[(size_t)M_ * D_];    // Q in (B,H,S,HD) layout
__device__ float g_ctx[(size_t)M_ * D_];  // attention context in (B,S,D) layout

__device__ __forceinline__ uint32_t f2tf32(float x) {
    uint32_t u;
    asm("cvt.rna.tf32.f32 %0, %1;" : "=r"(u) : "f"(x));
    return u;
}

__device__ __forceinline__ void mma_tf32(float c[4], uint32_t a0, uint32_t a1,
                                         uint32_t a2, uint32_t a3,
                                         uint32_t b0, uint32_t b1) {
    asm volatile(
        "mma.sync.aligned.m16n8k8.row.col.f32.tf32.tf32.f32 "
        "{%0,%1,%2,%3}, {%4,%5,%6,%7}, {%8,%9}, {%0,%1,%2,%3};"
        : "+f"(c[0]), "+f"(c[1]), "+f"(c[2]), "+f"(c[3])
        : "r"(a0), "r"(a1), "r"(a2), "r"(a3), "r"(b0), "r"(b1));
}

// ---------------------------------------------------------------------------
// GEMM (tf32 tensor cores): Y = X @ W^T + bias.
// X:[M,K] row-major, W:[N,K] row-major, K = D_ = 2048.
// Block 128x128x32, 256 threads = 8 warps as 2(M) x 4(N), warp tile 64x32.
// Per warp: 4x4 grid of m16n8k8 mma.  Register-prefetch double buffering.
// reshape==1: Y written as (B,H,S,HD).
// ---------------------------------------------------------------------------
__global__ __launch_bounds__(256) void gemm_tf32(const float* __restrict__ X,
                                                 const float* __restrict__ W,
                                                 const float* __restrict__ bias,
                                                 float* __restrict__ Y,
                                                 int reshape)
{
    __shared__ uint32_t As[BM * LDW];   // [m][k] tf32 bits
    __shared__ uint32_t Bs[BN * LDW];   // [n][k] tf32 bits

    const int K    = D_;
    const int tid  = threadIdx.x;
    const int lane = tid & 31;
    const int warp = tid >> 5;
    const int wm   = warp >> 2;          // 0..1 -> 64-row slab
    const int wn   = warp & 3;           // 0..3 -> 32-col slab
    const int lr   = lane >> 2;          // 0..7
    const int lc   = lane & 3;           // 0..3
    const int m0   = blockIdx.y * BM;
    const int n0   = blockIdx.x * BN;

    // Loader mapping: thread covers 4 rows (stride 32) x one float4 of k.
    const int lrow = tid >> 3;           // 0..31
    const int lcol = (tid & 7) << 2;     // 0,4,...,28
    const float* Xp = X + (size_t)(m0 + lrow) * K + lcol;
    const float* Wp = W + (size_t)(n0 + lrow) * K + lcol;

    float acc[4][4][4];
#pragma unroll
    for (int i = 0; i < 4; i++)
#pragma unroll
        for (int j = 0; j < 4; j++)
#pragma unroll
            for (int c = 0; c < 4; c++) acc[i][j][c] = 0.f;

    float4 pa[4], pb[4];

    // Preload tile 0.
#pragma unroll
    for (int l = 0; l < 4; l++) {
        pa[l] = *reinterpret_cast<const float4*>(Xp + (size_t)(l * 32) * K);
        pb[l] = *reinterpret_cast<const float4*>(Wp + (size_t)(l * 32) * K);
    }
#pragma unroll
    for (int l = 0; l < 4; l++) {
        uint32_t* a = &As[(lrow + l * 32) * LDW + lcol];
        a[0] = f2tf32(pa[l].x); a[1] = f2tf32(pa[l].y);
        a[2] = f2tf32(pa[l].z); a[3] = f2tf32(pa[l].w);
        uint32_t* b = &Bs[(lrow + l * 32) * LDW + lcol];
        b[0] = f2tf32(pb[l].x); b[1] = f2tf32(pb[l].y);
        b[2] = f2tf32(pb[l].z); b[3] = f2tf32(pb[l].w);
    }
    __syncthreads();

    const int NKT = K / BK;   // 64
    for (int kt = 0; kt < NKT; ++kt) {
        const bool has_next = (kt + 1 < NKT);
        if (has_next) {
            const int ko = (kt + 1) * BK;
#pragma unroll
            for (int l = 0; l < 4; l++) {
                pa[l] = *reinterpret_cast<const float4*>(Xp + (size_t)(l * 32) * K + ko);
                pb[l] = *reinterpret_cast<const float4*>(Wp + (size_t)(l * 32) * K + ko);
            }
        }

        // Compute on current smem tile: 4 k-steps of 8.
#pragma unroll
        for (int ks = 0; ks < 4; ++ks) {
            const int k0 = ks * 8;
            uint32_t af[4][4], bf[4][2];
#pragma unroll
            for (int mf = 0; mf < 4; mf++) {
                const int r = wm * 64 + mf * 16 + lr;
                af[mf][0] = As[r * LDW + k0 + lc];
                af[mf][1] = As[(r + 8) * LDW + k0 + lc];
                af[mf][2] = As[r * LDW + k0 + 4 + lc];
                af[mf][3] = As[(r + 8) * LDW + k0 + 4 + lc];
            }
#pragma unroll
            for (int nf = 0; nf < 4; nf++) {
                const int n = wn * 32 + nf * 8 + lr;
                bf[nf][0] = Bs[n * LDW + k0 + lc];
                bf[nf][1] = Bs[n * LDW + k0 + 4 + lc];
            }
#pragma unroll
            for (int mf = 0; mf < 4; mf++)
#pragma unroll
                for (int nf = 0; nf < 4; nf++)
                    mma_tf32(acc[mf][nf], af[mf][0], af[mf][1], af[mf][2], af[mf][3],
                             bf[nf][0], bf[nf][1]);
        }
        __syncthreads();

        if (has_next) {
#pragma unroll
            for (int l = 0; l < 4; l++) {
                uint32_t* a = &As[(lrow + l * 32) * LDW + lcol];
                a[0] = f2tf32(pa[l].x); a[1] = f2tf32(pa[l].y);
                a[2] = f2tf32(pa[l].z); a[3] = f2tf32(pa[l].w);
                uint32_t* b = &Bs[(lrow + l * 32) * LDW + lcol];
                b[0] = f2tf32(pb[l].x); b[1] = f2tf32(pb[l].y);
                b[2] = f2tf32(pb[l].z); b[3] = f2tf32(pb[l].w);
            }
            __syncthreads();
        }
    }

    // Epilogue: C fragment (m16n8): c0 (lr, lc*2), c1 (lr, lc*2+1),
    // c2 (lr+8, lc*2), c3 (lr+8, lc*2+1).  Write float2 pairs + bias.
    const int hh = n0 >> 7;  // whole 128-wide n-tile lies in one head
#pragma unroll
    for (int mf = 0; mf < 4; mf++) {
#pragma unroll
        for (int nf = 0; nf < 4; nf++) {
            const int nloc = wn * 32 + nf * 8 + lc * 2;
            const int n    = n0 + nloc;
            const float b0 = bias[n];
            const float b1 = bias[n + 1];
#pragma unroll
            for (int half = 0; half < 2; half++) {
                const int m = m0 + wm * 64 + mf * 16 + lr + half * 8;
                const float v0 = acc[mf][nf][half * 2 + 0] + b0;
                const float v1 = acc[mf][nf][half * 2 + 1] + b1;
                size_t idx;
                if (reshape) {
                    const int bb = m >> 11;
                    const int ss = m & (S_ - 1);
                    const int hd = n & (HD_ - 1);
                    idx = (((size_t)(bb * H_ + hh)) * S_ + ss) * HD_ + hd;
                } else {
                    idx = (size_t)m * D_ + n;
                }
                *reinterpret_cast<float2*>(Y + idx) = make_float2(v0, v1);
            }
        }
    }
}

// ---------------------------------------------------------------------------
// Causal flash attention, fp32 (unchanged from round 0).
// ---------------------------------------------------------------------------
__global__ __launch_bounds__(256) void flash_attn(const float* __restrict__ Qg,
                                                  const float* __restrict__ Kg,
                                                  const float* __restrict__ Vg,
                                                  float* __restrict__ ctx)
{
    extern __shared__ float smf[];
    float* Qt   = smf;
    float* Kt   = Qt + 128 * QK_PAD;
    float* Vs   = Kt + 128 * QK_PAD;
    float* Ss   = Vs + 64 * V_PAD;
    float* mrow = Ss + 64 * S_PAD;
    float* lrow = mrow + 64;
    float* arow = lrow + 64;

    const int bh   = blockIdx.y;
    const int qt_i = blockIdx.x;
    const int q0   = qt_i * BR;
    const int tid  = threadIdx.x;
    const int tx   = tid & 15;
    const int ty   = tid >> 4;

    const float* Qb = Qg + ((size_t)bh * S_ + q0) * HD_;
    const float* Kb = Kg + (size_t)bh * S_ * HD_;
    const float* Vb = Vg + (size_t)bh * S_ * HD_;

#pragma unroll
    for (int l = 0; l < 8; ++l) {
        int f   = tid + l * 256;
        int row = f >> 5;
        int c4  = (f & 31) << 2;
        float4 v = *reinterpret_cast<const float4*>(Qb + (size_t)row * HD_ + c4);
        Qt[(c4 + 0) * QK_PAD + row] = v.x;
        Qt[(c4 + 1) * QK_PAD + row] = v.y;
        Qt[(c4 + 2) * QK_PAD + row] = v.z;
        Qt[(c4 + 3) * QK_PAD + row] = v.w;
    }
    if (tid < 64) { mrow[tid] = -1e30f; lrow[tid] = 0.f; }

    float o[4][8];
#pragma unroll
    for (int i = 0; i < 4; i++)
#pragma unroll
        for (int c = 0; c < 8; c++) o[i][c] = 0.f;

    const float scale = 0.08838834764831845f;

    const int ntiles = qt_i + 1;
    for (int t = 0; t < ntiles; ++t) {
        const int k0 = t * BC;
        __syncthreads();

#pragma unroll
        for (int l = 0; l < 8; ++l) {
            int f   = tid + l * 256;
            int row = f >> 5;
            int c4  = (f & 31) << 2;
            float4 kv = *reinterpret_cast<const float4*>(Kb + (size_t)(k0 + row) * HD_ + c4);
            Kt[(c4 + 0) * QK_PAD + row] = kv.x;
            Kt[(c4 + 1) * QK_PAD + row] = kv.y;
            Kt[(c4 + 2) * QK_PAD + row] = kv.z;
            Kt[(c4 + 3) * QK_PAD + row] = kv.w;
            float4 vv = *reinterpret_cast<const float4*>(Vb + (size_t)(k0 + row) * HD_ + c4);
            *reinterpret_cast<float4*>(Vs + row * V_PAD + c4) = vv;
        }
        __syncthreads();

        float sacc[4][4];
#pragma unroll
        for (int i = 0; i < 4; i++)
#pragma unroll
            for (int j = 0; j < 4; j++) sacc[i][j] = 0.f;

#pragma unroll 4
        for (int kk = 0; kk < HD_; ++kk) {
            float4 a4 = *reinterpret_cast<const float4*>(Qt + kk * QK_PAD + ty * 4);
            float4 b4 = *reinterpret_cast<const float4*>(Kt + kk * QK_PAD + tx * 4);
            float a[4] = {a4.x, a4.y, a4.z, a4.w};
            float b[4] = {b4.x, b4.y, b4.z, b4.w};
#pragma unroll
            for (int i = 0; i < 4; i++)
#pragma unroll
                for (int j = 0; j < 4; j++)
                    sacc[i][j] = fmaf(a[i], b[j], sacc[i][j]);
        }

        const bool diag = (k0 == q0);
#pragma unroll
        for (int i = 0; i < 4; i++) {
#pragma unroll
            for (int j = 0; j < 4; j++) {
                float v = sacc[i][j] * scale;
                if (diag && (tx * 4 + j) > (ty * 4 + i)) v += -1e9f;
                Ss[(ty * 4 + i) * S_PAD + tx * 4 + j] = v;
            }
        }
        __syncthreads();

        if (tid < 64) {
            float* srow = Ss + tid * S_PAD;
            float tm = srow[0];
#pragma unroll 8
            for (int j = 1; j < BC; ++j) tm = fmaxf(tm, srow[j]);
            float mo = mrow[tid];
            float mn = fmaxf(mo, tm);
            float al = __expf(mo - mn);
            float sum = 0.f;
#pragma unroll 8
            for (int j = 0; j < BC; ++j) {
                float p = __expf(srow[j] - mn);
                srow[j] = p;
                sum += p;
            }
            lrow[tid] = lrow[tid] * al + sum;
            mrow[tid] = mn;
            arow[tid] = al;
        }
        __syncthreads();

        float al[4];
#pragma unroll
        for (int i = 0; i < 4; i++) al[i] = arow[ty * 4 + i];
#pragma unroll
        for (int i = 0; i < 4; i++)
#pragma unroll
            for (int c = 0; c < 8; c++) o[i][c] *= al[i];

#pragma unroll 4
        for (int j = 0; j < BC; ++j) {
            float p[4];
#pragma unroll
            for (int i = 0; i < 4; i++) p[i] = Ss[(ty * 4 + i) * S_PAD + j];
            float4 v0 = *reinterpret_cast<const float4*>(Vs + j * V_PAD + tx * 8);
            float4 v1 = *reinterpret_cast<const float4*>(Vs + j * V_PAD + tx * 8 + 4);
            float vv[8] = {v0.x, v0.y, v0.z, v0.w, v1.x, v1.y, v1.z, v1.w};
#pragma unroll
            for (int i = 0; i < 4; i++)
#pragma unroll
                for (int c = 0; c < 8; c++)
                    o[i][c] = fmaf(p[i], vv[c], o[i][c]);
        }
    }

    const int bb = bh / H_;
    const int hh = bh % H_;
#pragma unroll
    for (int i = 0; i < 4; i++) {
        int r = ty * 4 + i;
        float inv = 1.0f / lrow[r];
        float* dst = ctx + ((size_t)bb * S_ + q0 + r) * D_ + hh * HD_ + tx * 8;
        float4 w0 = make_float4(o[i][0] * inv, o[i][1] * inv, o[i][2] * inv, o[i][3] * inv);
        float4 w1 = make_float4(o[i][4] * inv, o[i][5] * inv, o[i][6] * inv, o[i][7] * inv);
        *reinterpret_cast<float4*>(dst)     = w0;
        *reinterpret_cast<float4*>(dst + 4) = w1;
    }
}

// ---------------------------------------------------------------------------
// kernel_launch: QKV proj (tf32 TC) -> flash attention -> O proj (tf32 TC).
// Outputs packed: out (B,S,D) @0, k (B,H,S,HD) @OFF, v @2*OFF.
// ---------------------------------------------------------------------------
extern "C" void kernel_launch(void* const* d_in, const int* in_sizes, int n_in,
                              void* d_out, int out_size)
{
    const float* X  = (const float*)d_in[0];
    const float* Wq = (const float*)d_in[2];
    const float* bq = (const float*)d_in[3];
    const float* Wk = (const float*)d_in[4];
    const float* bk = (const float*)d_in[5];
    const float* Wv = (const float*)d_in[6];
    const float* bv = (const float*)d_in[7];
    const float* Wo = (const float*)d_in[8];
    const float* bo = (const float*)d_in[9];

    float* out = (float*)d_out;
    const size_t OFF = (size_t)B_ * S_ * D_;
    float* kout = out + OFF;
    float* vout = out + 2 * OFF;

    static float* qbuf = nullptr;
    static float* cbuf = nullptr;
    static const int SMEM = (2 * 128 * QK_PAD + 64 * V_PAD + 64 * S_PAD + 3 * 64) * (int)sizeof(float);
    if (qbuf == nullptr) {
        cudaGetSymbolAddress((void**)&qbuf, g_q);
        cudaGetSymbolAddress((void**)&cbuf, g_ctx);
        cudaFuncSetAttribute(flash_attn, cudaFuncAttributeMaxDynamicSharedMemorySize, SMEM);
    }

    dim3 gg(D_ / BN, M_ / BM);   // (16, 32)
    gemm_tf32<<<gg, 256>>>(X, Wq, bq, qbuf, 1);
    gemm_tf32<<<gg, 256>>>(X, Wk, bk, kout, 1);
    gemm_tf32<<<gg, 256>>>(X, Wv, bv, vout, 1);

    flash_attn<<<dim3(S_ / BR, B_ * H_), 256, SMEM>>>(qbuf, kout, vout, cbuf);

    gemm_tf32<<<gg, 256>>>(cbuf, Wo, bo, out, 0);
}

// round 5
// speedup vs baseline: 3.7698x; 1.9419x over previous
#include <cuda_runtime.h>
#include <math.h>
#include <stdint.h>

// Problem constants
#define B_  2
#define S_  2048
#define D_  2048
#define H_  16
#define HD_ 128
#define M_  (B_*S_)   // 4096 rows

// GEMM tiling (tf32 tensor-core path)
#define BM 128
#define BN 128
#define BK 32
#define LDW 36        // BK + 4 pad words

// Flash-attention tiling (tensor-core)
#define FBR 128       // query rows per block
#define FBC 64        // kv rows per tile
#define QLD 132       // pitch (words) for Q/K/V tiles: 128+4  (pitch mod 32 == 4)
#define PLD 68        // pitch (words) for score/prob tile: 64+4

// Scratch (device globals: allocation-free rule)
__device__ float g_q[(size_t)M_ * D_];    // Q in (B,H,S,HD) layout
__device__ float g_ctx[(size_t)M_ * D_];  // attention context in (B,S,D) layout

__device__ __forceinline__ uint32_t f2tf32(float x) {
    uint32_t u;
    asm("cvt.rna.tf32.f32 %0, %1;" : "=r"(u) : "f"(x));
    return u;
}

__device__ __forceinline__ void mma_tf32(float c[4], uint32_t a0, uint32_t a1,
                                         uint32_t a2, uint32_t a3,
                                         uint32_t b0, uint32_t b1) {
    asm volatile(
        "mma.sync.aligned.m16n8k8.row.col.f32.tf32.tf32.f32 "
        "{%0,%1,%2,%3}, {%4,%5,%6,%7}, {%8,%9}, {%0,%1,%2,%3};"
        : "+f"(c[0]), "+f"(c[1]), "+f"(c[2]), "+f"(c[3])
        : "r"(a0), "r"(a1), "r"(a2), "r"(a3), "r"(b0), "r"(b1));
}

// ---------------------------------------------------------------------------
// GEMM (tf32 tensor cores): Y = X @ W^T + bias.
// ---------------------------------------------------------------------------
__global__ __launch_bounds__(256) void gemm_tf32(const float* __restrict__ X,
                                                 const float* __restrict__ W,
                                                 const float* __restrict__ bias,
                                                 float* __restrict__ Y,
                                                 int reshape)
{
    __shared__ uint32_t As[BM * LDW];
    __shared__ uint32_t Bs[BN * LDW];

    const int K    = D_;
    const int tid  = threadIdx.x;
    const int lane = tid & 31;
    const int warp = tid >> 5;
    const int wm   = warp >> 2;
    const int wn   = warp & 3;
    const int lr   = lane >> 2;
    const int lc   = lane & 3;
    const int m0   = blockIdx.y * BM;
    const int n0   = blockIdx.x * BN;

    const int lrow = tid >> 3;
    const int lcol = (tid & 7) << 2;
    const float* Xp = X + (size_t)(m0 + lrow) * K + lcol;
    const float* Wp = W + (size_t)(n0 + lrow) * K + lcol;

    float acc[4][4][4];
#pragma unroll
    for (int i = 0; i < 4; i++)
#pragma unroll
        for (int j = 0; j < 4; j++)
#pragma unroll
            for (int c = 0; c < 4; c++) acc[i][j][c] = 0.f;

    float4 pa[4], pb[4];
#pragma unroll
    for (int l = 0; l < 4; l++) {
        pa[l] = *reinterpret_cast<const float4*>(Xp + (size_t)(l * 32) * K);
        pb[l] = *reinterpret_cast<const float4*>(Wp + (size_t)(l * 32) * K);
    }
#pragma unroll
    for (int l = 0; l < 4; l++) {
        uint32_t* a = &As[(lrow + l * 32) * LDW + lcol];
        a[0] = f2tf32(pa[l].x); a[1] = f2tf32(pa[l].y);
        a[2] = f2tf32(pa[l].z); a[3] = f2tf32(pa[l].w);
        uint32_t* b = &Bs[(lrow + l * 32) * LDW + lcol];
        b[0] = f2tf32(pb[l].x); b[1] = f2tf32(pb[l].y);
        b[2] = f2tf32(pb[l].z); b[3] = f2tf32(pb[l].w);
    }
    __syncthreads();

    const int NKT = K / BK;
    for (int kt = 0; kt < NKT; ++kt) {
        const bool has_next = (kt + 1 < NKT);
        if (has_next) {
            const int ko = (kt + 1) * BK;
#pragma unroll
            for (int l = 0; l < 4; l++) {
                pa[l] = *reinterpret_cast<const float4*>(Xp + (size_t)(l * 32) * K + ko);
                pb[l] = *reinterpret_cast<const float4*>(Wp + (size_t)(l * 32) * K + ko);
            }
        }
#pragma unroll
        for (int ks = 0; ks < 4; ++ks) {
            const int k0 = ks * 8;
            uint32_t af[4][4], bf[4][2];
#pragma unroll
            for (int mf = 0; mf < 4; mf++) {
                const int r = wm * 64 + mf * 16 + lr;
                af[mf][0] = As[r * LDW + k0 + lc];
                af[mf][1] = As[(r + 8) * LDW + k0 + lc];
                af[mf][2] = As[r * LDW + k0 + 4 + lc];
                af[mf][3] = As[(r + 8) * LDW + k0 + 4 + lc];
            }
#pragma unroll
            for (int nf = 0; nf < 4; nf++) {
                const int n = wn * 32 + nf * 8 + lr;
                bf[nf][0] = Bs[n * LDW + k0 + lc];
                bf[nf][1] = Bs[n * LDW + k0 + 4 + lc];
            }
#pragma unroll
            for (int mf = 0; mf < 4; mf++)
#pragma unroll
                for (int nf = 0; nf < 4; nf++)
                    mma_tf32(acc[mf][nf], af[mf][0], af[mf][1], af[mf][2], af[mf][3],
                             bf[nf][0], bf[nf][1]);
        }
        __syncthreads();
        if (has_next) {
#pragma unroll
            for (int l = 0; l < 4; l++) {
                uint32_t* a = &As[(lrow + l * 32) * LDW + lcol];
                a[0] = f2tf32(pa[l].x); a[1] = f2tf32(pa[l].y);
                a[2] = f2tf32(pa[l].z); a[3] = f2tf32(pa[l].w);
                uint32_t* b = &Bs[(lrow + l * 32) * LDW + lcol];
                b[0] = f2tf32(pb[l].x); b[1] = f2tf32(pb[l].y);
                b[2] = f2tf32(pb[l].z); b[3] = f2tf32(pb[l].w);
            }
            __syncthreads();
        }
    }

    const int hh = n0 >> 7;
#pragma unroll
    for (int mf = 0; mf < 4; mf++) {
#pragma unroll
        for (int nf = 0; nf < 4; nf++) {
            const int nloc = wn * 32 + nf * 8 + lc * 2;
            const int n    = n0 + nloc;
            const float b0 = bias[n];
            const float b1 = bias[n + 1];
#pragma unroll
            for (int half = 0; half < 2; half++) {
                const int m = m0 + wm * 64 + mf * 16 + lr + half * 8;
                const float v0 = acc[mf][nf][half * 2 + 0] + b0;
                const float v1 = acc[mf][nf][half * 2 + 1] + b1;
                size_t idx;
                if (reshape) {
                    const int bb = m >> 11;
                    const int ss = m & (S_ - 1);
                    const int hd = n & (HD_ - 1);
                    idx = (((size_t)(bb * H_ + hh)) * S_ + ss) * HD_ + hd;
                } else {
                    idx = (size_t)m * D_ + n;
                }
                *reinterpret_cast<float2*>(Y + idx) = make_float2(v0, v1);
            }
        }
    }
}

// ---------------------------------------------------------------------------
// Causal flash attention, tf32 tensor cores.
// ---------------------------------------------------------------------------
__global__ __launch_bounds__(256) void flash_tc(const float* __restrict__ Qg,
                                                const float* __restrict__ Kg,
                                                const float* __restrict__ Vg,
                                                float* __restrict__ ctx)
{
    extern __shared__ uint32_t smu[];
    uint32_t* Qs = smu;                       // [FBR][QLD] tf32
    uint32_t* Ks = Qs + FBR * QLD;            // [FBC][QLD] tf32
    uint32_t* Vs = Ks + FBC * QLD;            // [FBC][QLD] tf32
    float*    Ps = (float*)(Vs + FBC * QLD);  // [FBR][PLD] scores fp32 / probs tf32-bits
    float*    mrow = Ps + FBR * PLD;          // [FBR]
    float*    lrow = mrow + FBR;
    float*    arow = lrow + FBR;

    const int bh  = blockIdx.y;
    const int qt  = (int)gridDim.x - 1 - (int)blockIdx.x;   // heavy blocks first
    const int q0  = qt * FBR;
    const int tid = threadIdx.x;
    const int lane = tid & 31;
    const int warp = tid >> 5;
    const int wm = warp >> 1;      // 0..3 -> 32-row slab
    const int wn = warp & 1;       // 0..1
    const int lr = lane >> 2;      // 0..7
    const int lc = lane & 3;       // 0..3

    const float* Qb = Qg + ((size_t)bh * S_ + q0) * HD_;
    const float* Kb = Kg + (size_t)bh * S_ * HD_;
    const float* Vb = Vg + (size_t)bh * S_ * HD_;

    // Load Q tile (128x128) as tf32.
#pragma unroll
    for (int l = 0; l < 16; ++l) {
        int f   = tid + l * 256;
        int row = f >> 5;
        int c4  = (f & 31) << 2;
        float4 v = *reinterpret_cast<const float4*>(Qb + (size_t)row * HD_ + c4);
        *reinterpret_cast<uint4*>(&Qs[row * QLD + c4]) =
            make_uint4(f2tf32(v.x), f2tf32(v.y), f2tf32(v.z), f2tf32(v.w));
    }
    if (tid < FBR) { mrow[tid] = -1e30f; lrow[tid] = 0.f; }

    // O accumulator: warp tile 32(m) x 64(n) = 2 x 8 frags.
    float o[2][8][4];
#pragma unroll
    for (int i = 0; i < 2; i++)
#pragma unroll
        for (int j = 0; j < 8; j++)
#pragma unroll
            for (int c = 0; c < 4; c++) o[i][j][c] = 0.f;

    const float scale = 0.08838834764831845f;  // 1/sqrt(128)

    const int ntiles = 2 * qt + 2;
    for (int t = 0; t < ntiles; ++t) {
        const int k0 = t * FBC;
        __syncthreads();   // prior readers of Ks/Vs/Ps done

        // Load K,V tiles (64x128 each) as tf32.
#pragma unroll
        for (int l = 0; l < 8; ++l) {
            int f   = tid + l * 256;
            int row = f >> 5;
            int c4  = (f & 31) << 2;
            float4 kv = *reinterpret_cast<const float4*>(Kb + (size_t)(k0 + row) * HD_ + c4);
            *reinterpret_cast<uint4*>(&Ks[row * QLD + c4]) =
                make_uint4(f2tf32(kv.x), f2tf32(kv.y), f2tf32(kv.z), f2tf32(kv.w));
            float4 vv = *reinterpret_cast<const float4*>(Vb + (size_t)(k0 + row) * HD_ + c4);
            *reinterpret_cast<uint4*>(&Vs[row * QLD + c4]) =
                make_uint4(f2tf32(vv.x), f2tf32(vv.y), f2tf32(vv.z), f2tf32(vv.w));
        }
        __syncthreads();

        // S = Q @ K^T : warp tile 32x32, frags 2(m16) x 4(n8), K-dim 128.
        float sacc[2][4][4];
#pragma unroll
        for (int i = 0; i < 2; i++)
#pragma unroll
            for (int j = 0; j < 4; j++)
#pragma unroll
                for (int c = 0; c < 4; c++) sacc[i][j][c] = 0.f;

#pragma unroll
        for (int ks = 0; ks < 16; ++ks) {
            const int k = ks * 8;
            uint32_t af[2][4], bf[4][2];
#pragma unroll
            for (int mf = 0; mf < 2; mf++) {
                const int r = wm * 32 + mf * 16 + lr;
                af[mf][0] = Qs[r * QLD + k + lc];
                af[mf][1] = Qs[(r + 8) * QLD + k + lc];
                af[mf][2] = Qs[r * QLD + k + 4 + lc];
                af[mf][3] = Qs[(r + 8) * QLD + k + 4 + lc];
            }
#pragma unroll
            for (int nf = 0; nf < 4; nf++) {
                const int n = wn * 32 + nf * 8 + lr;
                bf[nf][0] = Ks[n * QLD + k + lc];
                bf[nf][1] = Ks[n * QLD + k + 4 + lc];
            }
#pragma unroll
            for (int mf = 0; mf < 2; mf++)
#pragma unroll
                for (int nf = 0; nf < 4; nf++)
                    mma_tf32(sacc[mf][nf], af[mf][0], af[mf][1], af[mf][2], af[mf][3],
                             bf[nf][0], bf[nf][1]);
        }

        // Scale (+ causal mask on diagonal tiles), stash scores in Ps.
        const bool needmask = (k0 + FBC - 1 > q0);   // only last two tiles
#pragma unroll
        for (int mf = 0; mf < 2; mf++) {
#pragma unroll
            for (int nf = 0; nf < 4; nf++) {
#pragma unroll
                for (int c = 0; c < 4; c++) {
                    const int rloc = wm * 32 + mf * 16 + lr + (c >> 1) * 8;
                    const int cloc = wn * 32 + nf * 8 + lc * 2 + (c & 1);
                    float v = sacc[mf][nf][c] * scale;
                    if (needmask && (k0 + cloc) > (q0 + rloc)) v = -1e9f;
                    Ps[rloc * PLD + cloc] = v;
                }
            }
        }
        __syncthreads();

        // Online softmax (one thread per row); write probs back as tf32 bits.
        if (tid < FBR) {
            float* srow = Ps + tid * PLD;
            uint32_t* prow = (uint32_t*)srow;
            float tm = srow[0];
#pragma unroll 8
            for (int j = 1; j < FBC; ++j) tm = fmaxf(tm, srow[j]);
            float mo = mrow[tid];
            float mn = fmaxf(mo, tm);
            float al = __expf(mo - mn);
            float sum = 0.f;
#pragma unroll 8
            for (int j = 0; j < FBC; ++j) {
                float p = __expf(srow[j] - mn);
                sum += p;
                prow[j] = f2tf32(p);
            }
            lrow[tid] = lrow[tid] * al + sum;
            mrow[tid] = mn;
            arow[tid] = al;
        }
        __syncthreads();

        // Rescale O by alpha, then O += P @ V.
        {
            float al0 = arow[wm * 32 + lr];
            float al1 = arow[wm * 32 + lr + 8];
            float al2 = arow[wm * 32 + 16 + lr];
            float al3 = arow[wm * 32 + 16 + lr + 8];
#pragma unroll
            for (int nf = 0; nf < 8; nf++) {
                o[0][nf][0] *= al0; o[0][nf][1] *= al0;
                o[0][nf][2] *= al1; o[0][nf][3] *= al1;
                o[1][nf][0] *= al2; o[1][nf][1] *= al2;
                o[1][nf][2] *= al3; o[1][nf][3] *= al3;
            }
        }

        const uint32_t* Pb = (const uint32_t*)Ps;
#pragma unroll
        for (int ks = 0; ks < 8; ++ks) {
            const int k = ks * 8;
            uint32_t af[2][4], bf[8][2];
#pragma unroll
            for (int mf = 0; mf < 2; mf++) {
                const int r = wm * 32 + mf * 16 + lr;
                af[mf][0] = Pb[r * PLD + k + lc];
                af[mf][1] = Pb[(r + 8) * PLD + k + lc];
                af[mf][2] = Pb[r * PLD + k + 4 + lc];
                af[mf][3] = Pb[(r + 8) * PLD + k + 4 + lc];
            }
#pragma unroll
            for (int nf = 0; nf < 8; nf++) {
                const int n = wn * 64 + nf * 8 + lr;
                bf[nf][0] = Vs[(k + lc) * QLD + n];
                bf[nf][1] = Vs[(k + 4 + lc) * QLD + n];
            }
#pragma unroll
            for (int mf = 0; mf < 2; mf++)
#pragma unroll
                for (int nf = 0; nf < 8; nf++)
                    mma_tf32(o[mf][nf], af[mf][0], af[mf][1], af[mf][2], af[mf][3],
                             bf[nf][0], bf[nf][1]);
        }
    }

    __syncthreads();

    // Epilogue: normalize rows by 1/l and write ctx in (B,S,D).
    const int bb = bh / H_;
    const int hh = bh % H_;
#pragma unroll
    for (int mf = 0; mf < 2; mf++) {
#pragma unroll
        for (int half = 0; half < 2; half++) {
            const int rloc = wm * 32 + mf * 16 + lr + half * 8;
            const float inv = 1.0f / lrow[rloc];
            float* dst = ctx + ((size_t)bb * S_ + q0 + rloc) * D_ + hh * HD_;
#pragma unroll
            for (int nf = 0; nf < 8; nf++) {
                const int cloc = wn * 64 + nf * 8 + lc * 2;
                *reinterpret_cast<float2*>(dst + cloc) =
                    make_float2(o[mf][nf][half * 2 + 0] * inv,
                                o[mf][nf][half * 2 + 1] * inv);
            }
        }
    }
}

// ---------------------------------------------------------------------------
// kernel_launch
// ---------------------------------------------------------------------------
extern "C" void kernel_launch(void* const* d_in, const int* in_sizes, int n_in,
                              void* d_out, int out_size)
{
    const float* X  = (const float*)d_in[0];
    const float* Wq = (const float*)d_in[2];
    const float* bq = (const float*)d_in[3];
    const float* Wk = (const float*)d_in[4];
    const float* bk = (const float*)d_in[5];
    const float* Wv = (const float*)d_in[6];
    const float* bv = (const float*)d_in[7];
    const float* Wo = (const float*)d_in[8];
    const float* bo = (const float*)d_in[9];

    float* out = (float*)d_out;
    const size_t OFF = (size_t)B_ * S_ * D_;
    float* kout = out + OFF;
    float* vout = out + 2 * OFF;

    static float* qbuf = nullptr;
    static float* cbuf = nullptr;
    static const int FSMEM = (FBR * QLD + 2 * FBC * QLD + FBR * PLD + 3 * FBR) * (int)sizeof(uint32_t);
    if (qbuf == nullptr) {
        cudaGetSymbolAddress((void**)&qbuf, g_q);
        cudaGetSymbolAddress((void**)&cbuf, g_ctx);
        cudaFuncSetAttribute(flash_tc, cudaFuncAttributeMaxDynamicSharedMemorySize, FSMEM);
    }

    dim3 gg(D_ / BN, M_ / BM);   // (16, 32)
    gemm_tf32<<<gg, 256>>>(X, Wq, bq, qbuf, 1);
    gemm_tf32<<<gg, 256>>>(X, Wk, bk, kout, 1);
    gemm_tf32<<<gg, 256>>>(X, Wv, bv, vout, 1);

    flash_tc<<<dim3(S_ / FBR, B_ * H_), 256, FSMEM>>>(qbuf, kout, vout, cbuf);

    gemm_tf32<<<gg, 256>>>(cbuf, Wo, bo, out, 0);
}